// round 3
// baseline (speedup 1.0000x reference)
#include <cuda_runtime.h>
#include <cuda_bf16.h>

// Problem constants (fixed by the reference):
//   x:   (4, 5, 1024, 1024) float32
//   LUT: (1, 5, 9,9,9,9,9)  float32  -> flat (5, 59049)
//   out: (4, 5, 1024, 1024) float32
#define DIMV  9
#define NENT  59049            // 9^5
#define ENT_STRIDE 8           // pad each entry (5 channels) to 8 floats = one 32B sector
#define HW    (1024 * 1024)
#define NPIX  (4 * 1024 * 1024)
#define LUT_ELEMS (5 * NENT)   // 295245

// Repacked LUT: channel-innermost, 32B-aligned entries. 59049*8*4B = 1.89 MB (lives in L2).
__device__ __align__(16) float g_lutp[NENT * ENT_STRIDE];

// ---------------------------------------------------------------------------
// Kernel 1: repack LUT[c][i] (channel-major) -> g_lutp[i*8 + c] (entry-major)
// ---------------------------------------------------------------------------
__global__ void repack_kernel(const float* __restrict__ lut) {
    int i = blockIdx.x * blockDim.x + threadIdx.x;
    if (i >= NENT) return;
    float4 v;
    v.x = lut[0 * NENT + i];
    v.y = lut[1 * NENT + i];
    v.z = lut[2 * NENT + i];
    v.w = lut[3 * NENT + i];
    float v4 = lut[4 * NENT + i];
    float4* dst = reinterpret_cast<float4*>(&g_lutp[(size_t)i * ENT_STRIDE]);
    dst[0] = v;
    dst[1] = make_float4(v4, 0.0f, 0.0f, 0.0f);
}

// ---------------------------------------------------------------------------
// Kernel 2: one thread per pixel. 16 corner-pairs; lerp along dim 4 in regs.
// Each LUT entry is one aligned 32B sector = two float4 loads; corner pair
// (dim-4 lo/hi) = adjacent entries e and e+1 -> one 64B span, 4x LDG.128.
// ---------------------------------------------------------------------------
__global__ __launch_bounds__(256) void pglut_kernel(const float* __restrict__ x,
                                                    float* __restrict__ out) {
    int p = blockIdx.x * blockDim.x + threadIdx.x;
    if (p >= NPIX) return;
    int b  = p >> 20;          // HW = 2^20
    int hw = p & (HW - 1);

    const float* xp = x + (size_t)b * 5 * HW + hw;

    int   idx[5];
    float fr[5];
#pragma unroll
    for (int d = 0; d < 5; d++) {
        float xs = xp[(size_t)d * HW] * 8.0f;      // (DIM-1) = 8
        float fi = floorf(xs);
        fi = fminf(fmaxf(fi, 0.0f), 7.0f);          // clip(floor, 0, DIM-2)
        idx[d] = (int)fi;
        fr[d]  = xs - fi;                            // matches reference (can exceed 1 at edge)
    }

    int base = (((idx[0] * 9 + idx[1]) * 9 + idx[2]) * 9 + idx[3]) * 9 + idx[4];

    // Hierarchical corner weights over dims 0..3 (dim 4 handled by lerp).
    float w01[4], w23[4];
    {
        float a0 = 1.0f - fr[0], a1 = fr[0];
        float b0 = 1.0f - fr[1], b1 = fr[1];
        float c0 = 1.0f - fr[2], c1 = fr[2];
        float d0 = 1.0f - fr[3], d1 = fr[3];
        w01[0] = a0 * b0; w01[1] = a0 * b1; w01[2] = a1 * b0; w01[3] = a1 * b1;
        w23[0] = c0 * d0; w23[1] = c0 * d1; w23[2] = c1 * d0; w23[3] = c1 * d1;
    }
    float f4 = fr[4];

    float a0 = 0.0f, a1 = 0.0f, a2 = 0.0f, a3 = 0.0f, a4 = 0.0f;

    const float4* __restrict__ L4 = reinterpret_cast<const float4*>(g_lutp);

#pragma unroll
    for (int k = 0; k < 16; k++) {
        const int c0 = (k >> 3) & 1;
        const int c1 = (k >> 2) & 1;
        const int c2 = (k >> 1) & 1;
        const int c3 = k & 1;
        int e = base + c0 * 6561 + c1 * 729 + c2 * 81 + c3 * 9;

        // entry e (lo) and entry e+1 (hi): each one aligned 32B sector (2x float4)
        float4 loA = __ldg(&L4[(size_t)e * 2]);
        float4 loB = __ldg(&L4[(size_t)e * 2 + 1]);
        float4 hiA = __ldg(&L4[(size_t)e * 2 + 2]);
        float4 hiB = __ldg(&L4[(size_t)e * 2 + 3]);

        float wk = w01[k >> 2] * w23[k & 3];

        a0 = fmaf(wk, fmaf(f4, hiA.x - loA.x, loA.x), a0);
        a1 = fmaf(wk, fmaf(f4, hiA.y - loA.y, loA.y), a1);
        a2 = fmaf(wk, fmaf(f4, hiA.z - loA.z, loA.z), a2);
        a3 = fmaf(wk, fmaf(f4, hiA.w - loA.w, loA.w), a3);
        a4 = fmaf(wk, fmaf(f4, hiB.x - loB.x, loB.x), a4);
    }

    float* op = out + (size_t)b * 5 * HW + hw;
    op[0 * HW] = a0;
    op[1 * HW] = a1;
    op[2 * HW] = a2;
    op[3 * HW] = a3;
    op[4 * HW] = a4;
}

// ---------------------------------------------------------------------------
// Launch
// ---------------------------------------------------------------------------
extern "C" void kernel_launch(void* const* d_in, const int* in_sizes, int n_in,
                              void* d_out, int out_size) {
    const float* x   = (const float*)d_in[0];
    const float* lut = (const float*)d_in[1];
    // Defensive: identify inputs by size (x has 20971520 elems, LUT 295245).
    if (n_in >= 2 && in_sizes[0] == LUT_ELEMS) {
        lut = (const float*)d_in[0];
        x   = (const float*)d_in[1];
    }
    float* out = (float*)d_out;

    repack_kernel<<<(NENT + 255) / 256, 256>>>(lut);
    pglut_kernel<<<NPIX / 256, 256>>>(x, out);
}

// round 6
// speedup vs baseline: 1.2953x; 1.2953x over previous
#include <cuda_runtime.h>
#include <cuda_bf16.h>

// Problem constants (fixed by the reference):
//   x:   (4, 5, 1024, 1024) float32
//   LUT: (1, 5, 9,9,9,9,9)  float32  -> flat (5, 59049)
//   out: (4, 5, 1024, 1024) float32
#define NENT      59049          // 9^5
#define HW        (1024 * 1024)
#define NPIX      (4 * 1024 * 1024)
#define LUT_ELEMS (5 * NENT)     // 295245
#define NBLK012   729            // 9^3 corner triples over dims 0-2
#define NCELL34   64             // 8x8 cells over dims 3,4
#define TILE_F    24             // floats per tile: 16 (ch0-3 x 4 corners) + 4 (ch4) + 4 pad

// Tiled LUT: for each (i0,i1,i2) corner-triple and (i3,i4) cell, the 2x2
// corner block over dims (3,4), channel-packed. 729*64*24*4B = 4.48 MB.
__device__ __align__(16) float g_lutp[NBLK012 * NCELL34 * TILE_F];

// ---------------------------------------------------------------------------
// Kernel 1: repack channel-major LUT[c][e] -> (i3,i4)-cell tiles.
// One thread per tile (46656 threads): 20 scattered reads, 24 contiguous writes.
// ---------------------------------------------------------------------------
__global__ void repack_tiles(const float* __restrict__ lut) {
    int t = blockIdx.x * blockDim.x + threadIdx.x;
    if (t >= NBLK012 * NCELL34) return;
    int blk  = t >> 6;          // (i0*9+i1)*9+i2  in 0..728
    int cell = t & 63;          // i3*8+i4
    int i3 = cell >> 3, i4 = cell & 7;

    int e00 = blk * 81 + i3 * 9 + i4;   // entry index of corner (d3=0,d4=0)
    int eo[4] = { e00, e00 + 1, e00 + 9, e00 + 10 };  // (0,0),(0,1),(1,0),(1,1)

    float* dst = &g_lutp[(size_t)t * TILE_F];
#pragma unroll
    for (int c = 0; c < 4; c++) {
#pragma unroll
        for (int ch = 0; ch < 4; ch++)
            dst[c * 4 + ch] = lut[ch * NENT + eo[c]];
        dst[16 + c] = lut[4 * NENT + eo[c]];
    }
    dst[20] = 0.0f; dst[21] = 0.0f; dst[22] = 0.0f; dst[23] = 0.0f;
}

// ---------------------------------------------------------------------------
// Kernel 2: one thread per pixel. 8 corner-combos over dims 0-2; each reads
// one 2x2 (dims 3,4) tile with exactly 5 LDG.128 and does the bilinear lerp
// in registers. 40 gather loads/pixel = the 640B/pixel data floor.
// ---------------------------------------------------------------------------
__global__ __launch_bounds__(256) void pglut_kernel(const float* __restrict__ x,
                                                    float* __restrict__ out) {
    int p = blockIdx.x * blockDim.x + threadIdx.x;
    if (p >= NPIX) return;
    int b  = p >> 20;          // HW = 2^20
    int hw = p & (HW - 1);

    const float* xp = x + (size_t)b * 5 * HW + hw;

    int   idx[5];
    float fr[5];
#pragma unroll
    for (int d = 0; d < 5; d++) {
        float xs = xp[(size_t)d * HW] * 8.0f;      // (DIM-1) = 8
        float fi = floorf(xs);
        fi = fminf(fmaxf(fi, 0.0f), 7.0f);          // clip(floor, 0, DIM-2)
        idx[d] = (int)fi;
        fr[d]  = xs - fi;
    }

    int base012 = (idx[0] * 9 + idx[1]) * 9 + idx[2];
    int cell    = idx[3] * 8 + idx[4];

    // Weights over dims 0-2 (8 corner combos), hierarchical.
    float w[8];
    {
        float a0 = 1.0f - fr[0], a1 = fr[0];
        float b0 = 1.0f - fr[1], b1 = fr[1];
        float c0 = 1.0f - fr[2], c1 = fr[2];
        float ab00 = a0 * b0, ab01 = a0 * b1, ab10 = a1 * b0, ab11 = a1 * b1;
        w[0] = ab00 * c0; w[1] = ab00 * c1;
        w[2] = ab01 * c0; w[3] = ab01 * c1;
        w[4] = ab10 * c0; w[5] = ab10 * c1;
        w[6] = ab11 * c0; w[7] = ab11 * c1;
    }
    // Bilinear weights over dims 3,4.
    float f3 = fr[3], f4 = fr[4];
    float b00 = (1.0f - f3) * (1.0f - f4);
    float b01 = (1.0f - f3) * f4;
    float b10 = f3 * (1.0f - f4);
    float b11 = f3 * f4;

    float a0 = 0.0f, a1 = 0.0f, a2 = 0.0f, a3 = 0.0f, a4 = 0.0f;

    const float4* __restrict__ L = reinterpret_cast<const float4*>(g_lutp);

#pragma unroll
    for (int k = 0; k < 8; k++) {
        const int c0 = (k >> 2) & 1;
        const int c1 = (k >> 1) & 1;
        const int c2 = k & 1;
        int tile = (base012 + c0 * 81 + c1 * 9 + c2) * NCELL34 + cell;
        size_t fi = (size_t)tile * (TILE_F / 4);   // *6 float4s

        float4 q00 = __ldg(&L[fi + 0]);   // ch0-3 @ (d3,d4)=(0,0)
        float4 q01 = __ldg(&L[fi + 1]);   //               (0,1)
        float4 q10 = __ldg(&L[fi + 2]);   //               (1,0)
        float4 q11 = __ldg(&L[fi + 3]);   //               (1,1)
        float4 q4  = __ldg(&L[fi + 4]);   // ch4 @ 4 corners

        float wk = w[k];

        float m0 = fmaf(b00, q00.x, fmaf(b01, q01.x, fmaf(b10, q10.x, b11 * q11.x)));
        float m1 = fmaf(b00, q00.y, fmaf(b01, q01.y, fmaf(b10, q10.y, b11 * q11.y)));
        float m2 = fmaf(b00, q00.z, fmaf(b01, q01.z, fmaf(b10, q10.z, b11 * q11.z)));
        float m3 = fmaf(b00, q00.w, fmaf(b01, q01.w, fmaf(b10, q10.w, b11 * q11.w)));
        float m4 = fmaf(b00, q4.x,  fmaf(b01, q4.y,  fmaf(b10, q4.z,  b11 * q4.w)));

        a0 = fmaf(wk, m0, a0);
        a1 = fmaf(wk, m1, a1);
        a2 = fmaf(wk, m2, a2);
        a3 = fmaf(wk, m3, a3);
        a4 = fmaf(wk, m4, a4);
    }

    float* op = out + (size_t)b * 5 * HW + hw;
    op[0 * HW] = a0;
    op[1 * HW] = a1;
    op[2 * HW] = a2;
    op[3 * HW] = a3;
    op[4 * HW] = a4;
}

// ---------------------------------------------------------------------------
// Launch
// ---------------------------------------------------------------------------
extern "C" void kernel_launch(void* const* d_in, const int* in_sizes, int n_in,
                              void* d_out, int out_size) {
    const float* x   = (const float*)d_in[0];
    const float* lut = (const float*)d_in[1];
    // Defensive: identify inputs by size (x has 20971520 elems, LUT 295245).
    if (n_in >= 2 && in_sizes[0] == LUT_ELEMS) {
        lut = (const float*)d_in[0];
        x   = (const float*)d_in[1];
    }
    float* out = (float*)d_out;

    repack_tiles<<<(NBLK012 * NCELL34 + 255) / 256, 256>>>(lut);
    pglut_kernel<<<NPIX / 256, 256>>>(x, out);
}